// round 2
// baseline (speedup 1.0000x reference)
#include <cuda_runtime.h>
#include <math.h>

// ---------------- problem constants ----------------
#define BSZ 512
#define DD 100
#define TT 2
#define TOTAL_P 1086

// scratch buffer offsets (floats)
#define SCH1_L0 0ull
#define SCH1_L1 12697600ull
#define SCH1_L2 14643200ull
#define SPEC1   15052800ull
#define SCH0_L0 15155200ull
#define SPEC0   15564800ull
#define RAND_L0 15667200ull
#define RVIEW   15872000ull
#define SCRATCH_TOTAL 15923200ull

__device__ float g_buf[SCRATCH_TOTAL];

// ---------------- aggregation level kernel ----------------
// One launch per (pipeline, level). Fuses (gather | feats-read) + mean into the
// A-tile load of a 64x50 (K=100) shared-memory GEMM with 4x5 register tiles.
// grid = (ceil(Rout/64), 2 /*self|mean*/, T); block = 160 threads.

struct AggParams {
    const float* gtable;   // embedding table (mode 1/2)
    const float* prev;     // previous level feats (mode 0)
    float*       out;
    const int*   nodeids;
    const int*   neigh;
    const float* Ws;
    const float* Wn;
    int nseg;
    int s[5];      // input segment sizes s[0..nseg]
    int fan[4];
    int noff[5];   // neighbor offsets for input segments 1..nseg (modes 1/2)
    int nb_b, nb_t;
    int mode;      // 0 = feats, 1 = type_embed gather, 2 = rw_embed gather
    int idx;       // schema index into type_embed
    int Rin, Rout; // rows per t
};

#define AGG_SMEM 49072

__global__ __launch_bounds__(160) void agg_level_kernel(AggParams p) {
    extern __shared__ float sm[];
    float* sA    = sm;                    // [100][65]
    float* sW    = sm + 6500;             // [100][50]
    float* sInvr = sW + 5000;             // [64]
    int*   sSelf = (int*)(sInvr + 64);    // [64]
    int*   sFan  = sSelf + 64;            // [64]
    int*   sCoff = sFan + 64;             // [64*9]

    const int t    = blockIdx.z;
    const int half = blockIdx.y;          // 0 = self@Ws (cols 0..49), 1 = mean@Wn (cols 50..99)
    const int tid  = threadIdx.x;
    const int g0   = blockIdx.x * 64;

    // ---- phase 0: per-row metadata ----
    if (tid < 64) {
        int g = g0 + tid;
        int gg = (g < p.Rout) ? g : (p.Rout - 1);
        int kk = 0, off = 0;
        while (kk + 1 < p.nseg && gg >= off + BSZ * p.s[kk]) { off += BSZ * p.s[kk]; kk++; }
        int local = gg - off;
        int b = local / p.s[kk];
        int i = local - b * p.s[kk];
        int fan = p.fan[kk];
        sFan[tid]  = fan;
        sInvr[tid] = 1.0f / (float)fan;
        int nbase = b * p.nb_b + t * p.nb_t;
        if (half == 0) {
            int soff;
            if (p.mode == 0) {
                soff = (t * p.Rin + gg) * DD;
            } else {
                int id = (kk == 0) ? p.nodeids[b] : p.neigh[nbase + p.noff[kk] + i];
                soff = (p.mode == 1) ? (id * 400 + t * 200 + p.idx * 100) : id * DD;
            }
            sSelf[tid] = soff;
        } else {
            int off2 = off + BSZ * p.s[kk];
            if (p.mode == 0) {
                int base = (t * p.Rin + off2 + b * p.s[kk + 1] + i * fan) * DD;
                for (int j = 0; j < fan; j++) sCoff[tid * 9 + j] = base + j * DD;
            } else {
                int nb2 = nbase + p.noff[kk + 1] + i * fan;
                for (int j = 0; j < fan; j++) {
                    int id = p.neigh[nb2 + j];
                    sCoff[tid * 9 + j] = (p.mode == 1) ? (id * 400 + t * 200 + p.idx * 100)
                                                       : id * DD;
                }
            }
        }
    }
    // ---- load weights ----
    const float* Wsrc = (half == 0) ? p.Ws : p.Wn;
    for (int e = tid; e < 5000; e += 160) sW[e] = Wsrc[e];
    __syncthreads();

    // ---- phase 1: build A tile (k-major, stride 65) ----
    const float* src = (p.mode == 0) ? p.prev : p.gtable;
    if (half == 0) {
        for (int e = tid; e < 6400; e += 160) {
            int row = e / 100, k = e - row * 100;
            sA[k * 65 + row] = src[sSelf[row] + k];
        }
    } else {
        for (int e = tid; e < 6400; e += 160) {
            int row = e / 100, k = e - row * 100;
            int fan = sFan[row];
            float a = 0.f;
            for (int j = 0; j < fan; j++) a += src[sCoff[row * 9 + j] + k];
            sA[k * 65 + row] = a * sInvr[row];
        }
    }
    __syncthreads();

    // ---- phase 2: GEMM 64x50, K=100, thread tile 4x5 ----
    const int ct = tid % 10, rt = tid / 10;
    const int c0 = ct * 5, r0 = rt * 4;
    float acc[4][5];
#pragma unroll
    for (int r = 0; r < 4; r++)
#pragma unroll
        for (int c = 0; c < 5; c++) acc[r][c] = 0.f;

#pragma unroll 2
    for (int k = 0; k < 100; k++) {
        float a0 = sA[k * 65 + r0 + 0];
        float a1 = sA[k * 65 + r0 + 1];
        float a2 = sA[k * 65 + r0 + 2];
        float a3 = sA[k * 65 + r0 + 3];
        float w0 = sW[k * 50 + c0 + 0];
        float w1 = sW[k * 50 + c0 + 1];
        float w2 = sW[k * 50 + c0 + 2];
        float w3 = sW[k * 50 + c0 + 3];
        float w4 = sW[k * 50 + c0 + 4];
        acc[0][0] += a0 * w0; acc[0][1] += a0 * w1; acc[0][2] += a0 * w2; acc[0][3] += a0 * w3; acc[0][4] += a0 * w4;
        acc[1][0] += a1 * w0; acc[1][1] += a1 * w1; acc[1][2] += a1 * w2; acc[1][3] += a1 * w3; acc[1][4] += a1 * w4;
        acc[2][0] += a2 * w0; acc[2][1] += a2 * w1; acc[2][2] += a2 * w2; acc[2][3] += a2 * w3; acc[2][4] += a2 * w4;
        acc[3][0] += a3 * w0; acc[3][1] += a3 * w1; acc[3][2] += a3 * w2; acc[3][3] += a3 * w3; acc[3][4] += a3 * w4;
    }

    float* outb = p.out + (size_t)t * p.Rout * DD + half * 50;
#pragma unroll
    for (int r = 0; r < 4; r++) {
        int g = g0 + r0 + r;
        if (g < p.Rout) {
            float* op = outb + (size_t)g * DD + c0;
#pragma unroll
            for (int c = 0; c < 5; c++) op[c] = fmaxf(acc[r][c], 0.f);
        }
    }
}

// ---------------- attention + final kernel ----------------
// One block per batch element b (128 threads). Runs view-MHA (attn over T),
// meta-MHA (attn over V), pooling, reflect matvec, residual + L2 normalize.

__device__ __forceinline__ void mha_stage(
    float* X, float* LNX, float* Q, float* K, float* V, float* O,
    float* mu, float* rs, float* SC, float* ATT,
    int nb, int na,
    const float* __restrict__ Wq, const float* __restrict__ Wk,
    const float* __restrict__ Wv, const float* __restrict__ Wf,
    const float* __restrict__ gam, const float* __restrict__ bet, int tid)
{
    // layernorm stats (6 rows)
    if (tid < 6) {
        float s = 0.f;
        for (int d = 0; d < 100; d++) s += X[tid * 100 + d];
        float m = s * 0.01f;
        float v = 0.f;
        for (int d = 0; d < 100; d++) { float z = X[tid * 100 + d] - m; v += z * z; }
        mu[tid] = m;
        rs[tid] = rsqrtf(v * 0.01f + 1e-6f);
    }
    __syncthreads();
    for (int e = tid; e < 600; e += 128) {
        int r = e / 100, d = e - r * 100;
        LNX[e] = (X[e] - mu[r]) * rs[r] * gam[d] + bet[d];
    }
    __syncthreads();
    // Q (from LNX), K, V (from raw X)
    if (tid < 100) {
        float aq[6], ak[6], av[6];
#pragma unroll
        for (int r = 0; r < 6; r++) { aq[r] = 0.f; ak[r] = 0.f; av[r] = 0.f; }
        for (int k2 = 0; k2 < 100; k2++) {
            float wq = Wq[k2 * 100 + tid];
            float wk = Wk[k2 * 100 + tid];
            float wv = Wv[k2 * 100 + tid];
#pragma unroll
            for (int r = 0; r < 6; r++) {
                aq[r] += LNX[r * 100 + k2] * wq;
                ak[r] += X[r * 100 + k2] * wk;
                av[r] += X[r * 100 + k2] * wv;
            }
        }
#pragma unroll
        for (int r = 0; r < 6; r++) {
            Q[r * 100 + tid] = aq[r];
            K[r * 100 + tid] = ak[r];
            V[r * 100 + tid] = av[r];
        }
    }
    __syncthreads();
    // scores
    int nsc = nb * na * na;
    if (tid < nsc) {
        int bi = tid / (na * na), rem = tid - bi * na * na;
        int qa = rem / na, ka = rem - qa * na;
        const float* qp = Q + (bi * na + qa) * 100;
        const float* kp = K + (bi * na + ka) * 100;
        float s = 0.f;
        for (int d = 0; d < 100; d++) s += qp[d] * kp[d];
        SC[tid] = s * 0.1f;   // q / sqrt(100)
    }
    __syncthreads();
    // softmax over ka
    if (tid < nb * na) {
        int base = tid * na;
        float mx = -1e30f;
        for (int ka = 0; ka < na; ka++) mx = fmaxf(mx, SC[base + ka]);
        float ev[3], sum = 0.f;
        for (int ka = 0; ka < na; ka++) { ev[ka] = expf(SC[base + ka] - mx); sum += ev[ka]; }
        float inv = 1.0f / sum;
        for (int ka = 0; ka < na; ka++) ATT[base + ka] = ev[ka] * inv;
    }
    __syncthreads();
    // attn @ V
    if (tid < 100) {
        for (int bi = 0; bi < nb; bi++)
            for (int qa = 0; qa < na; qa++) {
                float acc = 0.f;
                for (int ka = 0; ka < na; ka++)
                    acc += ATT[(bi * na + qa) * na + ka] * V[(bi * na + ka) * 100 + tid];
                O[(bi * na + qa) * 100 + tid] = acc;
            }
    }
    __syncthreads();
    // @ Wf + residual, in place into X
    if (tid < 100) {
        float acc[6];
#pragma unroll
        for (int r = 0; r < 6; r++) acc[r] = 0.f;
        for (int k2 = 0; k2 < 100; k2++) {
            float wf = Wf[k2 * 100 + tid];
#pragma unroll
            for (int r = 0; r < 6; r++) acc[r] += O[r * 100 + k2] * wf;
        }
#pragma unroll
        for (int r = 0; r < 6; r++) X[r * 100 + tid] = acc[r] + X[r * 100 + tid];
    }
    __syncthreads();
}

__global__ __launch_bounds__(128) void attn_final_kernel(
    const float* __restrict__ spec0, const float* __restrict__ spec1,
    const float* __restrict__ rview,
    const int* __restrict__ edgetype, const int* __restrict__ nodeids,
    const float* __restrict__ base_embed, const float* __restrict__ reflect,
    const float* __restrict__ vWq, const float* __restrict__ vWk,
    const float* __restrict__ vWv, const float* __restrict__ vWf,
    const float* __restrict__ vg, const float* __restrict__ vb,
    const float* __restrict__ mWq, const float* __restrict__ mWk,
    const float* __restrict__ mWv, const float* __restrict__ mWf,
    const float* __restrict__ mg, const float* __restrict__ mb,
    float* __restrict__ outp)
{
    const int b = blockIdx.x;
    const int tid = threadIdx.x;
    __shared__ float X[600], LNX[600], Q[600], K[600], V[600], O[600];
    __shared__ float mu[6], rs[6], SC[18], ATT[18];
    __shared__ float SEL[100], RES[200], part[128];

    // load X rows r = v*2 + t  (view stage layout)
    for (int e = tid; e < 600; e += 128) {
        int r = e / 100, d = e - r * 100;
        int v = r >> 1, t = r & 1;
        float val;
        if (v == 0)      val = spec0[(t * BSZ + b) * DD + d];
        else if (v == 1) val = spec1[(t * BSZ + b) * DD + d];
        else             val = rview[b * DD + d];
        X[e] = val;
    }
    __syncthreads();

    // view attention: batch over v (nb=3), attend over t (na=2)
    mha_stage(X, LNX, Q, K, V, O, mu, rs, SC, ATT, 3, 2, vWq, vWk, vWv, vWf, vg, vb, tid);

    // reorder rows v*2+t -> t*3+v
    for (int e = tid; e < 600; e += 128) Q[e] = X[e];
    __syncthreads();
    for (int e = tid; e < 600; e += 128) {
        int r = e / 100, d = e - r * 100;
        int t = r / 3, v = r - t * 3;
        X[e] = Q[(v * 2 + t) * 100 + d];
    }
    __syncthreads();

    // meta attention: batch over t (nb=2), attend over v (na=3)
    mha_stage(X, LNX, Q, K, V, O, mu, rs, SC, ATT, 2, 3, mWq, mWk, mWv, mWf, mg, mb, tid);

    // pooled[t] = mean over v of X[t*3+v]; select type
    const int typ = edgetype[BSZ + b];
    if (tid < 100) {
        SEL[tid] = (X[(typ * 3 + 0) * 100 + tid] +
                    X[(typ * 3 + 1) * 100 + tid] +
                    X[(typ * 3 + 2) * 100 + tid]) * (1.0f / 3.0f);
    }
    __syncthreads();

    const int node = nodeids[b];
    for (int o = tid; o < 200; o += 128) {
        float acc = 0.f;
        const float* rp = reflect + (size_t)typ * 100 * 200 + o;
        for (int d = 0; d < 100; d++) acc += SEL[d] * rp[d * 200];
        RES[o] = base_embed[(size_t)node * 200 + o] + acc;
    }
    __syncthreads();
    float ps = 0.f;
    for (int o = tid; o < 200; o += 128) ps += RES[o] * RES[o];
    part[tid] = ps;
    __syncthreads();
    if (tid == 0) {
        float s = 0.f;
        for (int i = 0; i < 128; i++) s += part[i];
        part[0] = 1.0f / fmaxf(sqrtf(s), 1e-12f);
    }
    __syncthreads();
    float inv = part[0];
    for (int o = tid; o < 200; o += 128) outp[(size_t)b * 200 + o] = RES[o] * inv;
}

// ---------------- host launcher ----------------
extern "C" void kernel_launch(void* const* d_in, const int* in_sizes, int n_in,
                              void* d_out, int out_size) {
    const int*   nodeids    = (const int*)d_in[0];
    const int*   edgetype   = (const int*)d_in[1];
    const int*   neighbors  = (const int*)d_in[2];
    const int*   rneigh     = (const int*)d_in[3];
    const float* base_embed = (const float*)d_in[4];
    const float* type_embed = (const float*)d_in[5];
    const float* rw_embed   = (const float*)d_in[6];
    const float* reflect    = (const float*)d_in[7];
    const float* agg0_self  = (const float*)d_in[8];
    const float* agg0_neigh = (const float*)d_in[9];
    const float* agg1_self  = (const float*)d_in[10];
    const float* agg1_neigh = (const float*)d_in[11];
    const float* rand_self  = (const float*)d_in[12];
    const float* rand_neighw= (const float*)d_in[13];
    const float* vWq = (const float*)d_in[14];
    const float* vWk = (const float*)d_in[15];
    const float* vWv = (const float*)d_in[16];
    const float* vWf = (const float*)d_in[17];
    const float* vg  = (const float*)d_in[18];
    const float* vb  = (const float*)d_in[19];
    const float* mWq = (const float*)d_in[20];
    const float* mWk = (const float*)d_in[21];
    const float* mWv = (const float*)d_in[22];
    const float* mWf = (const float*)d_in[23];
    const float* mg  = (const float*)d_in[24];
    const float* mb  = (const float*)d_in[25];
    float* outp = (float*)d_out;

    float* buf = nullptr;
    cudaGetSymbolAddress((void**)&buf, g_buf);

    AggParams p;
    p.nodeids = nodeids;

    auto launch = [&](const AggParams& pp, int zdim) {
        dim3 grid((pp.Rout + 63) / 64, 2, zdim);
        agg_level_kernel<<<grid, 160, AGG_SMEM>>>(pp);
    };

    // ---- schema 1 (idx=1, parts [3,15,105,945], base 18) ----
    {   // level 0 (gather)
        p.gtable = type_embed; p.prev = nullptr; p.out = buf + SCH1_L0;
        p.neigh = neighbors; p.Ws = agg1_self; p.Wn = agg1_neigh;
        p.nseg = 4;
        int s[5] = {1, 3, 15, 105, 945};  for (int i = 0; i < 5; i++) p.s[i] = s[i];
        int f[4] = {3, 5, 7, 9};          for (int i = 0; i < 4; i++) p.fan[i] = f[i];
        int no[5] = {0, 18, 21, 36, 141}; for (int i = 0; i < 5; i++) p.noff[i] = no[i];
        p.nb_b = 2 * TOTAL_P; p.nb_t = TOTAL_P; p.mode = 1; p.idx = 1;
        p.Rin = 0; p.Rout = BSZ * 124;
        launch(p, 2);
    }
    {   // level 1
        p.gtable = nullptr; p.prev = buf + SCH1_L0; p.out = buf + SCH1_L1;
        p.Ws = agg1_self + 5000; p.Wn = agg1_neigh + 5000;
        p.nseg = 3;
        int s[5] = {1, 3, 15, 105, 0}; for (int i = 0; i < 5; i++) p.s[i] = s[i];
        int f[4] = {3, 5, 7, 0};       for (int i = 0; i < 4; i++) p.fan[i] = f[i];
        p.mode = 0; p.Rin = BSZ * 124; p.Rout = BSZ * 19;
        launch(p, 2);
    }
    {   // level 2
        p.prev = buf + SCH1_L1; p.out = buf + SCH1_L2;
        p.Ws = agg1_self + 10000; p.Wn = agg1_neigh + 10000;
        p.nseg = 2;
        int s[5] = {1, 3, 15, 0, 0}; for (int i = 0; i < 5; i++) p.s[i] = s[i];
        int f[4] = {3, 5, 0, 0};     for (int i = 0; i < 4; i++) p.fan[i] = f[i];
        p.mode = 0; p.Rin = BSZ * 19; p.Rout = BSZ * 4;
        launch(p, 2);
    }
    {   // level 3 -> spec1
        p.prev = buf + SCH1_L2; p.out = buf + SPEC1;
        p.Ws = agg1_self + 15000; p.Wn = agg1_neigh + 15000;
        p.nseg = 1;
        int s[5] = {1, 3, 0, 0, 0}; for (int i = 0; i < 5; i++) p.s[i] = s[i];
        int f[4] = {3, 0, 0, 0};    for (int i = 0; i < 4; i++) p.fan[i] = f[i];
        p.mode = 0; p.Rin = BSZ * 4; p.Rout = BSZ;
        launch(p, 2);
    }
    // ---- schema 0 (idx=0, parts [3,15], base 0) ----
    {   // level 0 (gather)
        p.gtable = type_embed; p.prev = nullptr; p.out = buf + SCH0_L0;
        p.Ws = agg0_self; p.Wn = agg0_neigh;
        p.nseg = 2;
        int s[5] = {1, 3, 15, 0, 0}; for (int i = 0; i < 5; i++) p.s[i] = s[i];
        int f[4] = {3, 5, 0, 0};     for (int i = 0; i < 4; i++) p.fan[i] = f[i];
        int no[5] = {0, 0, 3, 0, 0}; for (int i = 0; i < 5; i++) p.noff[i] = no[i];
        p.nb_b = 2 * TOTAL_P; p.nb_t = TOTAL_P; p.mode = 1; p.idx = 0;
        p.Rin = 0; p.Rout = BSZ * 4;
        launch(p, 2);
    }
    {   // level 1 -> spec0
        p.prev = buf + SCH0_L0; p.out = buf + SPEC0;
        p.Ws = agg0_self + 5000; p.Wn = agg0_neigh + 5000;
        p.nseg = 1;
        int s[5] = {1, 3, 0, 0, 0}; for (int i = 0; i < 5; i++) p.s[i] = s[i];
        int f[4] = {3, 0, 0, 0};    for (int i = 0; i < 4; i++) p.fan[i] = f[i];
        p.mode = 0; p.Rin = BSZ * 4; p.Rout = BSZ;
        launch(p, 2);
    }
    // ---- random-walk view ----
    {   // level 0 (gather from rw_embed)
        p.gtable = rw_embed; p.prev = nullptr; p.out = buf + RAND_L0;
        p.neigh = rneigh; p.Ws = rand_self; p.Wn = rand_neighw;
        p.nseg = 2;
        int s[5] = {1, 3, 15, 0, 0}; for (int i = 0; i < 5; i++) p.s[i] = s[i];
        int f[4] = {3, 5, 0, 0};     for (int i = 0; i < 4; i++) p.fan[i] = f[i];
        int no[5] = {0, 0, 3, 0, 0}; for (int i = 0; i < 5; i++) p.noff[i] = no[i];
        p.nb_b = 18; p.nb_t = 0; p.mode = 2; p.idx = 0;
        p.Rin = 0; p.Rout = BSZ * 4;
        launch(p, 1);
    }
    {   // level 1 -> rview
        p.prev = buf + RAND_L0; p.out = buf + RVIEW;
        p.Ws = rand_self + 5000; p.Wn = rand_neighw + 5000;
        p.nseg = 1;
        int s[5] = {1, 3, 0, 0, 0}; for (int i = 0; i < 5; i++) p.s[i] = s[i];
        int f[4] = {3, 0, 0, 0};    for (int i = 0; i < 4; i++) p.fan[i] = f[i];
        p.mode = 0; p.Rin = BSZ * 4; p.Rout = BSZ;
        launch(p, 1);
    }

    // ---- attention + final ----
    attn_final_kernel<<<BSZ, 128>>>(
        buf + SPEC0, buf + SPEC1, buf + RVIEW,
        edgetype, nodeids, base_embed, reflect,
        vWq, vWk, vWv, vWf, vg, vb,
        mWq, mWk, mWv, mWf, mg, mb,
        outp);
}

// round 3
// speedup vs baseline: 1.5859x; 1.5859x over previous
#include <cuda_runtime.h>
#include <math.h>

// ---------------- problem constants ----------------
#define BSZ 512
#define DD 100
#define TOTAL_P 1086

// scratch buffer offsets (floats)
#define SCH1_L0 0ull
#define SCH1_L1 12697600ull
#define SCH1_L2 14643200ull
#define SPEC1   15052800ull
#define SCH0_L0 15155200ull
#define SPEC0   15564800ull
#define RAND_L0 15667200ull
#define RVIEW   15872000ull
#define SCRATCH_TOTAL 15923200ull

__device__ float g_buf[SCRATCH_TOTAL];

typedef unsigned long long ull;

__device__ __forceinline__ ull fma2(ull a, ull b, ull c) {
    ull d;
    asm("fma.rn.f32x2 %0, %1, %2, %3;" : "=l"(d) : "l"(a), "l"(b), "l"(c));
    return d;
}
__device__ __forceinline__ ull pack2(float a) {
    ull d;
    asm("mov.b64 %0, {%1, %1};" : "=l"(d) : "f"(a));
    return d;
}
__device__ __forceinline__ void unpack2(ull v, float& lo, float& hi) {
    asm("mov.b64 {%0, %1}, %2;" : "=f"(lo), "=f"(hi) : "l"(v));
}

// ---------------- multi-job aggregation kernel ----------------
// Each block: 64 output rows x 100 cols. Builds self A-tile and neigh-mean
// A-tile (float4 gathers, fan loop fully unrolled/predicated for MLP), then a
// 64x100 (K=100) GEMM with fma.rn.f32x2 packed math.
// Jobs for independent pipelines are merged into one launch via a job table.

struct Job {
    const float* gsrc;     // gather table (mode 1/2) or prev-level feats (mode 0)
    float*       out;
    const float* Ws;
    const float* Wn;
    const int*   neigh;
    int mode;              // 0 = feats, 1 = type_embed, 2 = rw_embed
    int idx;               // schema index (mode 1)
    int nseg;
    int s[5];
    int fan[4];
    int noff[5];
    int nb_b, nb_t;
    int Rout;              // rows per t
    int Rin;               // input rows per t (mode 0)
    int rows;              // Rout * T_job
    int blk0;              // first block index of this job
};

struct MultiParams {
    Job job[3];
    int njobs;
    const int* nodeids;
};

// shared layout (floats)
#define SM_AS   0
#define SM_AM   6400
#define SM_W    12800
#define SM_SELF 22800   // int[64]
#define SM_FAN  22864   // int[64]
#define SM_COFF 22928   // int[64*9]
#define SM_INVF 23504   // float[64]
#define SM_FLOATS 23568
#define AGG_SMEM_BYTES (SM_FLOATS * 4)

__global__ __launch_bounds__(160) void agg_multi_kernel(MultiParams p) {
    extern __shared__ float sm[];
    float* sAs  = sm + SM_AS;
    float* sAm  = sm + SM_AM;
    float* sW   = sm + SM_W;
    int*   sSelf = (int*)(sm + SM_SELF);
    int*   sFan  = (int*)(sm + SM_FAN);
    int*   sCoff = (int*)(sm + SM_COFF);
    float* sInvF = sm + SM_INVF;

    const int tid = threadIdx.x;

    // job select
    int j = 0;
    if (p.njobs > 1 && (int)blockIdx.x >= p.job[1].blk0) j = 1;
    if (p.njobs > 2 && (int)blockIdx.x >= p.job[2].blk0) j = 2;
    Job jb = p.job[j];
    const int R0 = (blockIdx.x - jb.blk0) * 64;

    // ---- weights: [k][100] = [Ws | Wn], float2 granularity ----
    {
        const float* Ws = jb.Ws;
        const float* Wn = jb.Wn;
        for (int e = tid; e < 5000; e += 160) {
            int k = e / 50, pr = e - k * 50;
            int c = pr * 2;
            float2 v;
            if (c < 50) v = *(const float2*)(Ws + k * 50 + c);
            else        v = *(const float2*)(Wn + k * 50 + (c - 50));
            *(float2*)&sW[k * 100 + c] = v;
        }
    }

    // ---- per-row metadata ----
    if (tid < 64) {
        int R = R0 + tid;
        if (R >= jb.rows) R = jb.rows - 1;
        int t = (R >= jb.Rout) ? 1 : 0;
        int g = R - t * jb.Rout;
        int kk = 0, off = 0;
        while (kk + 1 < jb.nseg && g >= off + BSZ * jb.s[kk]) { off += BSZ * jb.s[kk]; kk++; }
        int local = g - off;
        int b = local / jb.s[kk];
        int i = local - b * jb.s[kk];
        int fan = jb.fan[kk];
        sFan[tid]  = fan;
        sInvF[tid] = 1.0f / (float)fan;
        // self offset
        int soff;
        if (jb.mode == 0) {
            soff = (t * jb.Rin + g) * DD;
        } else {
            int id = (kk == 0) ? p.nodeids[b]
                               : jb.neigh[b * jb.nb_b + t * jb.nb_t + jb.noff[kk] + i];
            soff = (jb.mode == 1) ? (id * 400 + t * 200 + jb.idx * 100) : id * DD;
        }
        sSelf[tid] = soff;
        // child offsets
        if (jb.mode == 0) {
            int off2 = off + BSZ * jb.s[kk];
            int base = (t * jb.Rin + off2 + b * jb.s[kk + 1] + i * fan) * DD;
            for (int jj = 0; jj < fan; jj++) sCoff[tid * 9 + jj] = base + jj * DD;
        } else {
            int nb2 = b * jb.nb_b + t * jb.nb_t + jb.noff[kk + 1] + i * fan;
            for (int jj = 0; jj < fan; jj++) {
                int id = jb.neigh[nb2 + jj];
                sCoff[tid * 9 + jj] = (jb.mode == 1) ? (id * 400 + t * 200 + jb.idx * 100)
                                                     : id * DD;
            }
        }
    }
    __syncthreads();

    // ---- A tiles, float4 granularity: items = (row, k4), 64*25 = 1600 ----
    const float* src = jb.gsrc;
    for (int e = tid; e < 1600; e += 160) {
        int row = e / 25, k4 = e - row * 25;
        float4 v = *(const float4*)(src + sSelf[row] + k4 * 4);
        int kb = k4 * 4;
        sAs[(kb + 0) * 64 + row] = v.x;
        sAs[(kb + 1) * 64 + row] = v.y;
        sAs[(kb + 2) * 64 + row] = v.z;
        sAs[(kb + 3) * 64 + row] = v.w;
    }
    for (int e = tid; e < 1600; e += 160) {
        int row = e / 25, k4 = e - row * 25;
        int f = sFan[row];
        const int* co = sCoff + row * 9;
        float x = 0.f, y = 0.f, z = 0.f, w = 0.f;
#pragma unroll
        for (int jj = 0; jj < 9; jj++) {
            if (jj < f) {
                float4 v = *(const float4*)(src + co[jj] + k4 * 4);
                x += v.x; y += v.y; z += v.z; w += v.w;
            }
        }
        float iv = sInvF[row];
        int kb = k4 * 4;
        sAm[(kb + 0) * 64 + row] = x * iv;
        sAm[(kb + 1) * 64 + row] = y * iv;
        sAm[(kb + 2) * 64 + row] = z * iv;
        sAm[(kb + 3) * 64 + row] = w * iv;
    }
    __syncthreads();

    // ---- GEMM 64x100, K=100; thread tile 4 rows x 10 cols (f32x2) ----
    const int ct = tid % 10, rt = tid / 10;
    const int c0 = ct * 10, r0 = rt * 4;
    const float* Ab = (ct < 5) ? sAs : sAm;

    ull acc[4][5];
#pragma unroll
    for (int r = 0; r < 4; r++)
#pragma unroll
        for (int q = 0; q < 5; q++) acc[r][q] = 0ull;

#pragma unroll 2
    for (int k = 0; k < 100; k++) {
        const float* ap = Ab + k * 64 + r0;
        ull a0 = pack2(ap[0]);
        ull a1 = pack2(ap[1]);
        ull a2 = pack2(ap[2]);
        ull a3 = pack2(ap[3]);
        const ull* wp = (const ull*)&sW[k * 100 + c0];
        ull w0 = wp[0], w1 = wp[1], w2 = wp[2], w3 = wp[3], w4 = wp[4];
        acc[0][0] = fma2(a0, w0, acc[0][0]); acc[0][1] = fma2(a0, w1, acc[0][1]);
        acc[0][2] = fma2(a0, w2, acc[0][2]); acc[0][3] = fma2(a0, w3, acc[0][3]);
        acc[0][4] = fma2(a0, w4, acc[0][4]);
        acc[1][0] = fma2(a1, w0, acc[1][0]); acc[1][1] = fma2(a1, w1, acc[1][1]);
        acc[1][2] = fma2(a1, w2, acc[1][2]); acc[1][3] = fma2(a1, w3, acc[1][3]);
        acc[1][4] = fma2(a1, w4, acc[1][4]);
        acc[2][0] = fma2(a2, w0, acc[2][0]); acc[2][1] = fma2(a2, w1, acc[2][1]);
        acc[2][2] = fma2(a2, w2, acc[2][2]); acc[2][3] = fma2(a2, w3, acc[2][3]);
        acc[2][4] = fma2(a2, w4, acc[2][4]);
        acc[3][0] = fma2(a3, w0, acc[3][0]); acc[3][1] = fma2(a3, w1, acc[3][1]);
        acc[3][2] = fma2(a3, w2, acc[3][2]); acc[3][3] = fma2(a3, w3, acc[3][3]);
        acc[3][4] = fma2(a3, w4, acc[3][4]);
    }

    // ---- epilogue: relu + store ----
#pragma unroll
    for (int r = 0; r < 4; r++) {
        int R = R0 + r0 + r;
        if (R < jb.rows) {
            int t = (R >= jb.Rout) ? 1 : 0;
            int g = R - t * jb.Rout;
            float* op = jb.out + (size_t)(t * jb.Rout + g) * DD + c0;
#pragma unroll
            for (int q = 0; q < 5; q++) {
                float lo, hi;
                unpack2(acc[r][q], lo, hi);
                float2 o;
                o.x = fmaxf(lo, 0.f);
                o.y = fmaxf(hi, 0.f);
                *(float2*)(op + 2 * q) = o;
            }
        }
    }
}

// ---------------- attention + final kernel ----------------
__device__ __forceinline__ void mha_stage(
    float* X, float* LNX, float* Q, float* K, float* V, float* O,
    float* mu, float* rs, float* SC, float* ATT,
    int nb, int na,
    const float* __restrict__ Wq, const float* __restrict__ Wk,
    const float* __restrict__ Wv, const float* __restrict__ Wf,
    const float* __restrict__ gam, const float* __restrict__ bet, int tid)
{
    if (tid < 6) {
        float s = 0.f;
        for (int d = 0; d < 100; d++) s += X[tid * 100 + d];
        float m = s * 0.01f;
        float v = 0.f;
        for (int d = 0; d < 100; d++) { float z = X[tid * 100 + d] - m; v += z * z; }
        mu[tid] = m;
        rs[tid] = rsqrtf(v * 0.01f + 1e-6f);
    }
    __syncthreads();
    for (int e = tid; e < 600; e += 128) {
        int r = e / 100, d = e - r * 100;
        LNX[e] = (X[e] - mu[r]) * rs[r] * gam[d] + bet[d];
    }
    __syncthreads();
    if (tid < 100) {
        float aq[6], ak[6], av[6];
#pragma unroll
        for (int r = 0; r < 6; r++) { aq[r] = 0.f; ak[r] = 0.f; av[r] = 0.f; }
        for (int k2 = 0; k2 < 100; k2++) {
            float wq = Wq[k2 * 100 + tid];
            float wk = Wk[k2 * 100 + tid];
            float wv = Wv[k2 * 100 + tid];
#pragma unroll
            for (int r = 0; r < 6; r++) {
                aq[r] += LNX[r * 100 + k2] * wq;
                ak[r] += X[r * 100 + k2] * wk;
                av[r] += X[r * 100 + k2] * wv;
            }
        }
#pragma unroll
        for (int r = 0; r < 6; r++) {
            Q[r * 100 + tid] = aq[r];
            K[r * 100 + tid] = ak[r];
            V[r * 100 + tid] = av[r];
        }
    }
    __syncthreads();
    int nsc = nb * na * na;
    if (tid < nsc) {
        int bi = tid / (na * na), rem = tid - bi * na * na;
        int qa = rem / na, ka = rem - qa * na;
        const float* qp = Q + (bi * na + qa) * 100;
        const float* kp = K + (bi * na + ka) * 100;
        float s = 0.f;
        for (int d = 0; d < 100; d++) s += qp[d] * kp[d];
        SC[tid] = s * 0.1f;
    }
    __syncthreads();
    if (tid < nb * na) {
        int base = tid * na;
        float mx = -1e30f;
        for (int ka = 0; ka < na; ka++) mx = fmaxf(mx, SC[base + ka]);
        float ev[3], sum = 0.f;
        for (int ka = 0; ka < na; ka++) { ev[ka] = expf(SC[base + ka] - mx); sum += ev[ka]; }
        float inv = 1.0f / sum;
        for (int ka = 0; ka < na; ka++) ATT[base + ka] = ev[ka] * inv;
    }
    __syncthreads();
    if (tid < 100) {
        for (int bi = 0; bi < nb; bi++)
            for (int qa = 0; qa < na; qa++) {
                float acc = 0.f;
                for (int ka = 0; ka < na; ka++)
                    acc += ATT[(bi * na + qa) * na + ka] * V[(bi * na + ka) * 100 + tid];
                O[(bi * na + qa) * 100 + tid] = acc;
            }
    }
    __syncthreads();
    if (tid < 100) {
        float acc[6];
#pragma unroll
        for (int r = 0; r < 6; r++) acc[r] = 0.f;
        for (int k2 = 0; k2 < 100; k2++) {
            float wf = Wf[k2 * 100 + tid];
#pragma unroll
            for (int r = 0; r < 6; r++) acc[r] += O[r * 100 + k2] * wf;
        }
#pragma unroll
        for (int r = 0; r < 6; r++) X[r * 100 + tid] = acc[r] + X[r * 100 + tid];
    }
    __syncthreads();
}

__global__ __launch_bounds__(128) void attn_final_kernel(
    const float* __restrict__ spec0, const float* __restrict__ spec1,
    const float* __restrict__ rview,
    const int* __restrict__ edgetype, const int* __restrict__ nodeids,
    const float* __restrict__ base_embed, const float* __restrict__ reflect,
    const float* __restrict__ vWq, const float* __restrict__ vWk,
    const float* __restrict__ vWv, const float* __restrict__ vWf,
    const float* __restrict__ vg, const float* __restrict__ vb,
    const float* __restrict__ mWq, const float* __restrict__ mWk,
    const float* __restrict__ mWv, const float* __restrict__ mWf,
    const float* __restrict__ mg, const float* __restrict__ mb,
    float* __restrict__ outp)
{
    const int b = blockIdx.x;
    const int tid = threadIdx.x;
    __shared__ float X[600], LNX[600], Q[600], K[600], V[600], O[600];
    __shared__ float mu[6], rs[6], SC[18], ATT[18];
    __shared__ float SEL[100], RES[200], part[128];

    for (int e = tid; e < 600; e += 128) {
        int r = e / 100, d = e - r * 100;
        int v = r >> 1, t = r & 1;
        float val;
        if (v == 0)      val = spec0[(t * BSZ + b) * DD + d];
        else if (v == 1) val = spec1[(t * BSZ + b) * DD + d];
        else             val = rview[b * DD + d];
        X[e] = val;
    }
    __syncthreads();

    mha_stage(X, LNX, Q, K, V, O, mu, rs, SC, ATT, 3, 2, vWq, vWk, vWv, vWf, vg, vb, tid);

    for (int e = tid; e < 600; e += 128) Q[e] = X[e];
    __syncthreads();
    for (int e = tid; e < 600; e += 128) {
        int r = e / 100, d = e - r * 100;
        int t = r / 3, v = r - t * 3;
        X[e] = Q[(v * 2 + t) * 100 + d];
    }
    __syncthreads();

    mha_stage(X, LNX, Q, K, V, O, mu, rs, SC, ATT, 2, 3, mWq, mWk, mWv, mWf, mg, mb, tid);

    const int typ = edgetype[BSZ + b];
    if (tid < 100) {
        SEL[tid] = (X[(typ * 3 + 0) * 100 + tid] +
                    X[(typ * 3 + 1) * 100 + tid] +
                    X[(typ * 3 + 2) * 100 + tid]) * (1.0f / 3.0f);
    }
    __syncthreads();

    const int node = nodeids[b];
    for (int o = tid; o < 200; o += 128) {
        float acc = 0.f;
        const float* rp = reflect + (size_t)typ * 100 * 200 + o;
        for (int d = 0; d < 100; d++) acc += SEL[d] * rp[d * 200];
        RES[o] = base_embed[(size_t)node * 200 + o] + acc;
    }
    __syncthreads();
    float ps = 0.f;
    for (int o = tid; o < 200; o += 128) ps += RES[o] * RES[o];
    part[tid] = ps;
    __syncthreads();
    if (tid == 0) {
        float s = 0.f;
        for (int i = 0; i < 128; i++) s += part[i];
        part[0] = 1.0f / fmaxf(sqrtf(s), 1e-12f);
    }
    __syncthreads();
    float inv = part[0];
    for (int o = tid; o < 200; o += 128) outp[(size_t)b * 200 + o] = RES[o] * inv;
}

// ---------------- host launcher ----------------
static void set_job(Job& j, const float* gsrc, float* out, const float* Ws, const float* Wn,
                    const int* neigh, int mode, int idx, int nseg,
                    const int* s, const int* fan, const int* noff,
                    int nb_b, int nb_t, int Rout, int Rin, int Tj, int blk0) {
    j.gsrc = gsrc; j.out = out; j.Ws = Ws; j.Wn = Wn; j.neigh = neigh;
    j.mode = mode; j.idx = idx; j.nseg = nseg;
    for (int i = 0; i < 5; i++) j.s[i] = s[i];
    for (int i = 0; i < 4; i++) j.fan[i] = fan[i];
    for (int i = 0; i < 5; i++) j.noff[i] = noff[i];
    j.nb_b = nb_b; j.nb_t = nb_t; j.Rout = Rout; j.Rin = Rin;
    j.rows = Rout * Tj; j.blk0 = blk0;
}

extern "C" void kernel_launch(void* const* d_in, const int* in_sizes, int n_in,
                              void* d_out, int out_size) {
    const int*   nodeids    = (const int*)d_in[0];
    const int*   edgetype   = (const int*)d_in[1];
    const int*   neighbors  = (const int*)d_in[2];
    const int*   rneigh     = (const int*)d_in[3];
    const float* base_embed = (const float*)d_in[4];
    const float* type_embed = (const float*)d_in[5];
    const float* rw_embed   = (const float*)d_in[6];
    const float* reflect    = (const float*)d_in[7];
    const float* agg0_self  = (const float*)d_in[8];
    const float* agg0_neigh = (const float*)d_in[9];
    const float* agg1_self  = (const float*)d_in[10];
    const float* agg1_neigh = (const float*)d_in[11];
    const float* rand_self  = (const float*)d_in[12];
    const float* rand_neighw= (const float*)d_in[13];
    const float* vWq = (const float*)d_in[14];
    const float* vWk = (const float*)d_in[15];
    const float* vWv = (const float*)d_in[16];
    const float* vWf = (const float*)d_in[17];
    const float* vg  = (const float*)d_in[18];
    const float* vb  = (const float*)d_in[19];
    const float* mWq = (const float*)d_in[20];
    const float* mWk = (const float*)d_in[21];
    const float* mWv = (const float*)d_in[22];
    const float* mWf = (const float*)d_in[23];
    const float* mg  = (const float*)d_in[24];
    const float* mb  = (const float*)d_in[25];
    float* outp = (float*)d_out;

    float* buf = nullptr;
    cudaGetSymbolAddress((void**)&buf, g_buf);

    cudaFuncSetAttribute(agg_multi_kernel,
                         cudaFuncAttributeMaxDynamicSharedMemorySize, AGG_SMEM_BYTES);

    const int s1[5]  = {1, 3, 15, 105, 945};
    const int f1[4]  = {3, 5, 7, 9};
    const int no1[5] = {0, 18, 21, 36, 141};
    const int s1b[5] = {1, 3, 15, 105, 0};
    const int f1b[4] = {3, 5, 7, 0};
    const int s0[5]  = {1, 3, 15, 0, 0};
    const int f0[4]  = {3, 5, 0, 0};
    const int no0[5] = {0, 0, 3, 0, 0};
    const int sT[5]  = {1, 3, 0, 0, 0};
    const int fT[4]  = {3, 0, 0, 0};
    const int noZ[5] = {0, 0, 0, 0, 0};

    MultiParams p;
    p.nodeids = nodeids;

    // ===== launch 1: all level-0 jobs =====
    {
        int b0 = 0;
        set_job(p.job[0], type_embed, buf + SCH1_L0, agg1_self, agg1_neigh, neighbors,
                1, 1, 4, s1, f1, no1, 2 * TOTAL_P, TOTAL_P, BSZ * 124, 0, 2, b0);
        b0 += (p.job[0].rows + 63) / 64;
        set_job(p.job[1], type_embed, buf + SCH0_L0, agg0_self, agg0_neigh, neighbors,
                1, 0, 2, s0, f0, no0, 2 * TOTAL_P, TOTAL_P, BSZ * 4, 0, 2, b0);
        b0 += (p.job[1].rows + 63) / 64;
        set_job(p.job[2], rw_embed, buf + RAND_L0, rand_self, rand_neighw, rneigh,
                2, 0, 2, s0, f0, no0, 18, 0, BSZ * 4, 0, 1, b0);
        b0 += (p.job[2].rows + 63) / 64;
        p.njobs = 3;
        agg_multi_kernel<<<b0, 160, AGG_SMEM_BYTES>>>(p);
    }
    // ===== launch 2: all level-1 jobs =====
    {
        int b0 = 0;
        set_job(p.job[0], buf + SCH1_L0, buf + SCH1_L1, agg1_self + 5000, agg1_neigh + 5000,
                nullptr, 0, 0, 3, s1b, f1b, noZ, 0, 0, BSZ * 19, BSZ * 124, 2, b0);
        b0 += (p.job[0].rows + 63) / 64;
        set_job(p.job[1], buf + SCH0_L0, buf + SPEC0, agg0_self + 5000, agg0_neigh + 5000,
                nullptr, 0, 0, 1, sT, fT, noZ, 0, 0, BSZ, BSZ * 4, 2, b0);
        b0 += (p.job[1].rows + 63) / 64;
        set_job(p.job[2], buf + RAND_L0, buf + RVIEW, rand_self + 5000, rand_neighw + 5000,
                nullptr, 0, 0, 1, sT, fT, noZ, 0, 0, BSZ, BSZ * 4, 1, b0);
        b0 += (p.job[2].rows + 63) / 64;
        p.njobs = 3;
        agg_multi_kernel<<<b0, 160, AGG_SMEM_BYTES>>>(p);
    }
    // ===== launch 3: schema1 level-2 =====
    {
        int b0 = 0;
        set_job(p.job[0], buf + SCH1_L1, buf + SCH1_L2, agg1_self + 10000, agg1_neigh + 10000,
                nullptr, 0, 0, 2, s0, f0, noZ, 0, 0, BSZ * 4, BSZ * 19, 2, b0);
        b0 += (p.job[0].rows + 63) / 64;
        p.njobs = 1;
        agg_multi_kernel<<<b0, 160, AGG_SMEM_BYTES>>>(p);
    }
    // ===== launch 4: schema1 level-3 =====
    {
        int b0 = 0;
        set_job(p.job[0], buf + SCH1_L2, buf + SPEC1, agg1_self + 15000, agg1_neigh + 15000,
                nullptr, 0, 0, 1, sT, fT, noZ, 0, 0, BSZ, BSZ * 4, 2, b0);
        b0 += (p.job[0].rows + 63) / 64;
        p.njobs = 1;
        agg_multi_kernel<<<b0, 160, AGG_SMEM_BYTES>>>(p);
    }

    // ===== launch 5: attention + final =====
    attn_final_kernel<<<BSZ, 128>>>(
        buf + SPEC0, buf + SPEC1, buf + RVIEW,
        edgetype, nodeids, base_embed, reflect,
        vWq, vWk, vWv, vWf, vg, vb,
        mWq, mWk, mWv, mWf, mg, mb,
        outp);
}